// round 12
// baseline (speedup 1.0000x reference)
#include <cuda_runtime.h>
#include <math.h>

#define BB 4
#define CC 256
#define NPIX 16384
#define HD 8
#define CPH 32
#define CRR 16
#define NIMG 1024
#define PITCH 129

typedef unsigned long long ull;

__device__ __forceinline__ ull pk(float lo, float hi) {
    ull r; asm("mov.b64 %0, {%1,%2};" : "=l"(r) : "f"(lo), "f"(hi)); return r;
}
__device__ __forceinline__ void upk(ull v, float& lo, float& hi) {
    asm("mov.b64 {%0,%1}, %2;" : "=f"(lo), "=f"(hi) : "l"(v));
}
__device__ __forceinline__ void fma2(ull& d, ull a, ull b) {
    asm("fma.rn.f32x2 %0, %1, %2, %3;" : "=l"(d) : "l"(a), "l"(b), "l"(d));
}

// ---------------- device scratch ----------------
__device__ float2 g_Xc[NIMG * NPIX];
__device__ float2 g_z[NIMG * NPIX];
__device__ float2 g_gXc[NIMG * NPIX];
__device__ float  g_outf[NIMG * NPIX];
__device__ float  g_outfl[NIMG * NPIX];
__device__ float  g_gram[BB * HD * CPH * CPH];
__device__ float  g_norm2[BB * CC];
__device__ float2 g_attn2[BB * HD * CPH * CPH];

__device__ __forceinline__ int brev3(int t) { return ((t & 1) << 2) | (t & 2) | ((t >> 2) & 1); }

// ---------------- 16-point FFT fully in registers ----------------
template<bool INV>
__device__ __forceinline__ void fft16_reg(float* xr, float* xi)
{
    #define SW_(i,j) { float t_=xr[i]; xr[i]=xr[j]; xr[j]=t_; t_=xi[i]; xi[i]=xi[j]; xi[j]=t_; }
    SW_(1,8) SW_(2,4) SW_(3,12) SW_(5,10) SW_(7,14) SW_(11,13)
    #undef SW_
    const float S = INV ? 1.f : -1.f;
    #pragma unroll
    for (int i = 0; i < 16; i += 2) {
        float ur = xr[i], ui = xi[i], vr = xr[i+1], vi = xi[i+1];
        xr[i] = ur + vr; xi[i] = ui + vi;
        xr[i+1] = ur - vr; xi[i+1] = ui - vi;
    }
    #pragma unroll
    for (int i = 0; i < 16; i += 4) {
        { float ur = xr[i], ui = xi[i], vr = xr[i+2], vi = xi[i+2];
          xr[i] = ur + vr; xi[i] = ui + vi; xr[i+2] = ur - vr; xi[i+2] = ui - vi; }
        { float ur = xr[i+1], ui = xi[i+1], vr = xr[i+3], vi = xi[i+3];
          float tr = -S * vi, ti = S * vr;
          xr[i+1] = ur + tr; xi[i+1] = ui + ti; xr[i+3] = ur - tr; xi[i+3] = ui - ti; }
    }
    {
        const float H = 0.70710678118654752f;
        const float w8r[4] = {1.f, H, 0.f, -H};
        const float w8i[4] = {0.f, H, 1.f, H};
        #pragma unroll
        for (int i = 0; i < 16; i += 8) {
            #pragma unroll
            for (int p = 0; p < 4; p++) {
                float wr = w8r[p], wi = S * w8i[p];
                float ur = xr[i+p], ui = xi[i+p], vr = xr[i+p+4], vi = xi[i+p+4];
                float tr = vr * wr - vi * wi, ti = vr * wi + vi * wr;
                xr[i+p] = ur + tr; xi[i+p] = ui + ti;
                xr[i+p+4] = ur - tr; xi[i+p+4] = ui - ti;
            }
        }
    }
    {
        const float C1 = 0.92387953251128674f, C2 = 0.70710678118654752f, C3 = 0.38268343236508978f;
        const float w16r[8] = {1.f, C1, C2, C3, 0.f, -C3, -C2, -C1};
        const float w16i[8] = {0.f, C3, C2, C1, 1.f, C1, C2, C3};
        #pragma unroll
        for (int p = 0; p < 8; p++) {
            float wr = w16r[p], wi = S * w16i[p];
            float ur = xr[p], ui = xi[p], vr = xr[p+8], vi = xi[p+8];
            float tr = vr * wr - vi * wi, ti = vr * wi + vi * wr;
            xr[p] = ur + tr; xi[p] = ui + ti;
            xr[p+8] = ur - tr; xi[p+8] = ui - ti;
        }
    }
}

// ---------------- 8-point cross-lane DIF FFT via shfl ----------------
template<bool INV>
__device__ __forceinline__ void xfft8(float* yr, float* yi, int t)
{
    const float S = INV ? 1.f : -1.f;
    const float H = 0.70710678118654752f;
    {
        int p = t & 3;
        float wr = (p == 0) ? 1.f : (p == 1) ? H : (p == 2) ? 0.f : -H;
        float wi = S * ((p == 0) ? 0.f : (p == 2) ? 1.f : H);
        bool hi = (t & 4) != 0;
        #pragma unroll
        for (int m = 0; m < 16; m++) {
            float pr = __shfl_xor_sync(0xffffffffu, yr[m], 4);
            float pi = __shfl_xor_sync(0xffffffffu, yi[m], 4);
            if (!hi) { yr[m] += pr; yi[m] += pi; }
            else {
                float dr = pr - yr[m], di = pi - yi[m];
                yr[m] = dr * wr - di * wi; yi[m] = dr * wi + di * wr;
            }
        }
    }
    {
        bool hi = (t & 2) != 0, odd = (t & 1) != 0;
        #pragma unroll
        for (int m = 0; m < 16; m++) {
            float pr = __shfl_xor_sync(0xffffffffu, yr[m], 2);
            float pi = __shfl_xor_sync(0xffffffffu, yi[m], 2);
            if (!hi) { yr[m] += pr; yi[m] += pi; }
            else {
                float dr = pr - yr[m], di = pi - yi[m];
                if (!odd) { yr[m] = dr; yi[m] = di; }
                else      { yr[m] = -S * di; yi[m] = S * dr; }
            }
        }
    }
    {
        bool hi = (t & 1) != 0;
        #pragma unroll
        for (int m = 0; m < 16; m++) {
            float pr = __shfl_xor_sync(0xffffffffu, yr[m], 1);
            float pi = __shfl_xor_sync(0xffffffffu, yi[m], 1);
            if (!hi) { yr[m] += pr; yi[m] += pi; }
            else     { yr[m] = pr - yr[m]; yi[m] = pi - yi[m]; }
        }
    }
}

// ---------------- 128-pt FFT over smem tile; group g, lane t in [0,8) ----------
template<bool INV, bool COLS>
__device__ __forceinline__ void fft128_reg(float* re, float* im, const float* twc, int g, int t)
{
    float xr[16], xi[16];
    #pragma unroll
    for (int m = 0; m < 16; m++) {
        int n = t + 8 * m;
        int idx = COLS ? (n * PITCH + g) : (g * PITCH + n);
        xr[m] = re[idx]; xi[m] = im[idx];
    }
    fft16_reg<INV>(xr, xi);
    #pragma unroll
    for (int m = 0; m < 16; m++) {
        int j = m * t;
        float cr = twc[2 * j], ci = twc[2 * j + 1];
        float wi = INV ? ci : -ci;
        float a = xr[m], b = xi[m];
        xr[m] = a * cr - b * wi;
        xi[m] = a * wi + b * cr;
    }
    xfft8<INV>(xr, xi, t);
    int s = brev3(t);
    #pragma unroll
    for (int m = 0; m < 16; m++) {
        int f = m + 16 * s;
        int idx = COLS ? (f * PITCH + g) : (g * PITCH + f);
        if (INV) { re[idx] = xr[m] * 0.0078125f; im[idx] = xi[m] * 0.0078125f; }
        else     { re[idx] = xr[m];              im[idx] = xi[m]; }
    }
}

#define FFT_SMEM_FLOATS (2 * 128 * PITCH + 512)
#define FFT_SMEM_BYTES  (FFT_SMEM_FLOATS * 4)
#define RZ_SMEM_FLOATS  (2 * 32 * PITCH + 512)
#define RZ_SMEM_BYTES   (RZ_SMEM_FLOATS * 4)

__device__ __forceinline__ void build_tw128(float* twc)
{
    for (int a = threadIdx.x; a < 128; a += blockDim.x) {
        float s, c;
        sincospif((float)a / 64.0f, &s, &c);
        twc[2 * a] = c; twc[2 * a + 1] = s;
    }
}

// ---------------- zero accumulators ----------------
__global__ void k_zero()
{
    int i = blockIdx.x * blockDim.x + threadIdx.x;
    if (i < BB * HD * CPH * CPH) g_gram[i] = 0.f;
    if (i < BB * CC) g_norm2[i] = 0.f;
}

// ---------------- kernel A: row FFT + twiddle + row iFFT -> z (32-row chunks) ----------------
__global__ void __launch_bounds__(256) k_rowfft_z(const float* __restrict__ x)
{
    extern __shared__ float sm[];
    float* re = sm;
    float* im = re + 32 * PITCH;
    float* t1 = im + 32 * PITCH;
    float* t2 = t1 + 256;

    build_tw128(t1);
    for (int a = threadIdx.x; a < 128; a += blockDim.x) {
        float s, c;
        sincospif((float)a / 8192.0f, &s, &c);
        t2[2 * a] = c; t2[2 * a + 1] = s;
    }

    int c = blockIdx.x;
    int img = blockIdx.y;
    const float* xin = x + (size_t)img * NPIX + (size_t)c * 32 * 128;
    int tid = threadIdx.x;
    int g = tid >> 3, t = tid & 7;

    #pragma unroll
    for (int it = 0; it < 16; it++) {
        int i = tid + it * 256;
        int lr = i >> 7, k = i & 127;
        re[lr * PITCH + k] = xin[lr * 128 + k];
        im[lr * PITCH + k] = 0.f;
    }
    __syncthreads();

    fft128_reg<false, false>(re, im, t1, g, t);
    __syncthreads();

    #pragma unroll
    for (int it = 0; it < 16; it++) {
        int i = tid + it * 256;
        int lr = i >> 7, f = i & 127;
        int r = c * 32 + lr;
        int j = f * r;
        int a = j >> 7, bI = j & 127;
        float wr = t1[2 * a] * t2[2 * bI] - t1[2 * a + 1] * t2[2 * bI + 1];
        float wi = t1[2 * a] * t2[2 * bI + 1] + t1[2 * a + 1] * t2[2 * bI];
        int idx = lr * PITCH + f;
        float xr_ = re[idx], xi_ = im[idx];
        re[idx] = xr_ * wr - xi_ * wi;
        im[idx] = xr_ * wi + xi_ * wr;
    }
    __syncthreads();

    fft128_reg<true, false>(re, im, t1, g, t);
    __syncthreads();

    float2* Z = g_z + (size_t)img * NPIX;
    #pragma unroll
    for (int it = 0; it < 16; it++) {
        int u = tid + it * 256;
        int lr = u & 31, m1 = u >> 5;
        Z[m1 * 128 + c * 32 + lr] = make_float2(re[lr * PITCH + m1], im[lr * PITCH + m1]);
    }
}

// ---------------- kernel B: full fft2(x) -> Xc (re-reads x; row FFT + col FFT) ----------------
__global__ void __launch_bounds__(1024, 1) k_fft2(const float* __restrict__ x)
{
    extern __shared__ float sm[];
    float* re = sm;
    float* im = re + 128 * PITCH;
    float* t1 = im + 128 * PITCH;
    build_tw128(t1);

    int img = blockIdx.x;
    const float* xin = x + (size_t)img * NPIX;
    int tid = threadIdx.x;
    int g = tid >> 3, t = tid & 7;

    #pragma unroll
    for (int it = 0; it < 16; it++) {
        int i = tid + it * 1024;
        int r = i >> 7, k = i & 127;
        re[r * PITCH + k] = xin[i];
        im[r * PITCH + k] = 0.f;
    }
    __syncthreads();

    fft128_reg<false, false>(re, im, t1, g, t);
    __syncthreads();
    fft128_reg<false, true>(re, im, t1, g, t);
    __syncthreads();

    float2* Xc = g_Xc + (size_t)img * NPIX;
    #pragma unroll
    for (int it = 0; it < 16; it++) {
        int i = tid + it * 1024;
        int r = i >> 7, k = i & 127;
        Xc[i] = make_float2(re[r * PITCH + k], im[r * PITCH + k]);
    }
}

// ---------------- gram + norms (f32x2, GSL=256) ----------------
#define GSL 256
#define APITCH 257
#define BPITCH 34
__global__ void __launch_bounds__(256) k_gram(const float* __restrict__ x)
{
    extern __shared__ float sm[];
    float* A  = sm;
    float* Bf = sm + CPH * APITCH;
    int p0 = blockIdx.x * GSL;
    int bh = blockIdx.y;
    int b = bh >> 3, head = bh & 7;
    const float* xb = x + (size_t)(b * CC + head * CPH) * NPIX;
    int tid = threadIdx.x;

    for (int i = tid; i < CPH * GSL; i += 256) {
        int d = i >> 8, jj = i & 255;
        int p = p0 + jj;
        A[d * APITCH + jj] = xb[(size_t)d * NPIX + p];
        int fr = (128 - (p >> 7)) & 127;
        int fw = (128 - (p & 127)) & 127;
        Bf[jj * BPITCH + d] = xb[(size_t)d * NPIX + fr * 128 + fw];
    }
    __syncthreads();

    if (tid < CPH) {
        float s = 0.f;
        for (int j = 0; j < GSL; j++) { float v = A[tid * APITCH + j]; s += v * v; }
        atomicAdd(&g_norm2[b * CC + head * CPH + tid], s);
    }

    int c0 = (tid >> 4) * 2;
    int d0 = (tid & 15) * 2;
    ull acc0 = 0, acc1 = 0;
    for (int j = 0; j < GSL; j++) {
        float a0 = A[c0 * APITCH + j];
        float a1 = A[(c0 + 1) * APITCH + j];
        ull bp = *(const ull*)&Bf[j * BPITCH + d0];
        fma2(acc0, pk(a0, a0), bp);
        fma2(acc1, pk(a1, a1), bp);
    }
    float v00, v01, v10, v11;
    upk(acc0, v00, v01); upk(acc1, v10, v11);
    float* G = g_gram + (size_t)bh * CPH * CPH;
    atomicAdd(&G[c0 * CPH + d0], v00);
    atomicAdd(&G[c0 * CPH + d0 + 1], v01);
    atomicAdd(&G[(c0 + 1) * CPH + d0], v10);
    atomicAdd(&G[(c0 + 1) * CPH + d0 + 1], v11);
}

// ---------------- softmax + 32-pt IFFT of attn ----------------
__global__ void k_attn(const float* __restrict__ temp)
{
    __shared__ float sP[CPH][CPH + 1];
    int bh = blockIdx.x;
    int b = bh >> 3, head = bh & 7;
    int tid = threadIdx.x;
    int c = tid >> 5, d = tid & 31;

    float G = g_gram[(bh * CPH + c) * CPH + d];
    float nc = fmaxf(128.f * sqrtf(g_norm2[b * CC + head * CPH + c]), 1e-12f);
    float nd = fmaxf(128.f * sqrtf(g_norm2[b * CC + head * CPH + d]), 1e-12f);
    float S = temp[head] * 16384.f * G / (nc * nd);

    float m = S;
    #pragma unroll
    for (int o = 16; o; o >>= 1) m = fmaxf(m, __shfl_xor_sync(0xffffffffu, m, o));
    float e = expf(S - m);
    float sum = e;
    #pragma unroll
    for (int o = 16; o; o >>= 1) sum += __shfl_xor_sync(0xffffffffu, sum, o);
    sP[c][d] = e / sum;
    __syncthreads();

    float ar = 0.f, ai = 0.f;
    #pragma unroll
    for (int cp = 0; cp < 32; cp++) {
        float s, cw;
        sincospif((float)(c * cp) / 16.0f, &s, &cw);
        float v = sP[cp][d];
        ar += v * cw - (1.0f / 32.0f) * s;
        ai += v * s + (1.0f / 32.0f) * cw;
    }
    g_attn2[(bh * CPH + c) * CPH + d] = make_float2(ar * (1.f / 32.f), ai * (1.f / 32.f));
}

// ---------------- out_f = | attn2 @ z | ----------------
#define OPX 256
#define ZPITCH 257
__global__ void __launch_bounds__(256) k_out2()
{
    extern __shared__ float smraw[];
    ull*    sAp = (ull*)smraw;
    float2* sZ  = (float2*)(smraw + CPH * CPH * 4);
    int bh = blockIdx.y;
    int b = bh >> 3, head = bh & 7;
    int p0 = blockIdx.x * OPX;
    int tid = threadIdx.x;

    for (int i = tid; i < CPH * CPH; i += 256) {
        float2 a = g_attn2[bh * CPH * CPH + i];
        sAp[i * 2 + 0] = pk(a.x, a.x);
        sAp[i * 2 + 1] = pk(a.y, a.y);
    }
    size_t base = (size_t)(b * CC + head * CPH) * NPIX + p0;
    for (int i = tid; i < CPH * OPX; i += 256) {
        int d = i >> 8, j = i & 255;
        sZ[d * ZPITCH + j] = g_z[base + (size_t)d * NPIX + j];
    }
    __syncthreads();

    int j = tid;
    ull acc[CPH];
    #pragma unroll
    for (int c = 0; c < CPH; c++) acc[c] = 0;

    for (int d = 0; d < CPH; d++) {
        float2 z = sZ[d * ZPITCH + j];
        ull zp = pk(z.x, z.y);
        ull zs = pk(-z.y, z.x);
        const ull* row = sAp + d * 2;
        #pragma unroll
        for (int c = 0; c < CPH; c++) {
            fma2(acc[c], row[c * 64 + 0], zp);
            fma2(acc[c], row[c * 64 + 1], zs);
        }
    }
    #pragma unroll
    for (int c = 0; c < CPH; c++) {
        float ar, ai; upk(acc[c], ar, ai);
        g_outf[(size_t)(b * CC + head * CPH + c) * NPIX + p0 + j] = sqrtf(ar * ar + ai * ai);
    }
}

// ---------------- fused gating ----------------
#define GPIX 32
#define XPITCH 33
__global__ void __launch_bounds__(256) k_gate(const float* __restrict__ w1, const float* __restrict__ b1,
                                              const float* __restrict__ bng, const float* __restrict__ bnb,
                                              const float* __restrict__ bnm, const float* __restrict__ bnv,
                                              const float* __restrict__ w2, const float* __restrict__ b2)
{
    extern __shared__ float sm[];
    float2* sxc = (float2*)sm;
    float*  sw1 = sm + CC * XPITCH * 2;
    float*  sw2 = sw1 + CRR * 257;
    float*  st  = sw2 + CC * 17;

    int b = blockIdx.y;
    int p0 = blockIdx.x * GPIX;
    int tid = threadIdx.x;

    for (int i = tid; i < CRR * CC; i += 256) {
        int j = i >> 8, ch = i & 255;
        sw1[j * 257 + ch] = w1[i];
    }
    for (int i = tid; i < CC * CRR; i += 256) {
        int ch = i >> 4, j = i & 15;
        sw2[ch * 17 + j] = w2[i];
    }
    const float2* Xc = g_Xc + (size_t)b * CC * NPIX;
    for (int i = tid; i < CC * GPIX; i += 256) {
        int ch = i >> 5, p = i & 31;
        sxc[ch * XPITCH + p] = Xc[(size_t)ch * NPIX + p0 + p];
    }
    __syncthreads();

    {
        int j = tid & 15, pp = tid >> 4;
        ull acc = 0;
        for (int ch = 0; ch < CC; ch++) {
            float w = sw1[j * 257 + ch];
            float x0 = sxc[ch * XPITCH + pp].x;
            float x1 = sxc[ch * XPITCH + pp + 16].x;
            fma2(acc, pk(w, w), pk(x0, x1));
        }
        float a0, a1; upk(acc, a0, a1);
        float scale = bng[j] * rsqrtf(bnv[j] + 1e-5f);
        float shift = bnb[j] + (b1[j] - bnm[j]) * scale;
        st[j * 33 + pp]      = fmaxf(a0 * scale + shift, 0.f);
        st[j * 33 + pp + 16] = fmaxf(a1 * scale + shift, 0.f);
    }
    __syncthreads();

    int p = tid & 31, cg = tid >> 5;
    float2* O = g_gXc + (size_t)b * CC * NPIX + p0;
    for (int cc = 0; cc < 32; cc++) {
        int ch = cg * 32 + cc;
        float acc = b2[ch];
        #pragma unroll
        for (int j = 0; j < CRR; j++)
            acc += sw2[ch * 17 + j] * st[j * 33 + p];
        float gate = 1.f / (1.f + __expf(-acc));
        float2 v = sxc[ch * XPITCH + p];
        O[(size_t)ch * NPIX + p] = make_float2(gate * v.x, gate * v.y);
    }
}

// ---------------- ifft2 + abs of gated spectrum ----------------
__global__ void __launch_bounds__(1024, 1) k_ifft2abs()
{
    extern __shared__ float sm[];
    float* re = sm;
    float* im = re + 128 * PITCH;
    float* t1 = im + 128 * PITCH;
    build_tw128(t1);

    int img = blockIdx.x;
    const float2* in = g_gXc + (size_t)img * NPIX;
    int tid = threadIdx.x;
    int g = tid >> 3, t = tid & 7;

    #pragma unroll
    for (int it = 0; it < 16; it++) {
        int i = tid + it * 1024;
        int r = i >> 7, k = i & 127;
        float2 v = in[i];
        re[r * PITCH + k] = v.x;
        im[r * PITCH + k] = v.y;
    }
    __syncthreads();

    fft128_reg<true, false>(re, im, t1, g, t);
    __syncthreads();
    fft128_reg<true, true>(re, im, t1, g, t);
    __syncthreads();

    float* out = g_outfl + (size_t)img * NPIX;
    #pragma unroll
    for (int it = 0; it < 16; it++) {
        int i = tid + it * 1024;
        int r = i >> 7, k = i & 127;
        float a = re[r * PITCH + k], bv = im[r * PITCH + k];
        out[i] = sqrtf(a * a + bv * bv);
    }
}

// ---------------- final projection: 128x128 tile, 8x8 per thread, f32x2 ----------------
#define PTM 128
#define PTN 128
#define PTK 16
#define SPITCH 132
__global__ void __launch_bounds__(256) k_proj(const float* __restrict__ pw, float* __restrict__ out)
{
    __shared__ float As[PTK][SPITCH];
    __shared__ float Bs[PTK][SPITCH];
    int b = blockIdx.z;
    int p0 = blockIdx.x * PTM;
    int o0 = blockIdx.y * PTN;
    int tid = threadIdx.x;
    int mf = (tid & 15) * 8;
    int nf = (tid >> 4) * 8;

    ull acc[8][4];
    #pragma unroll
    for (int n = 0; n < 8; n++)
        #pragma unroll
        for (int m = 0; m < 4; m++) acc[n][m] = 0;

    for (int k0 = 0; k0 < 512; k0 += PTK) {
        const float* src = (k0 < 256) ? g_outf : g_outfl;
        int cbase = k0 & 255;
        #pragma unroll
        for (int i = 0; i < 2; i++) {
            int u = tid + 256 * i;
            int k = u >> 5, pq = (u & 31) * 4;
            float4 v = *(const float4*)&src[((size_t)b * CC + cbase + k) * NPIX + p0 + pq];
            *(float4*)&As[k][pq] = v;
        }
        #pragma unroll
        for (int i = 0; i < 2; i++) {
            int u = tid + 256 * i;
            int o = u & 127, kq = (u >> 7) * 4;
            float4 v = *(const float4*)&pw[(size_t)(o0 + o) * 512 + k0 + kq];
            Bs[kq + 0][o] = v.x; Bs[kq + 1][o] = v.y;
            Bs[kq + 2][o] = v.z; Bs[kq + 3][o] = v.w;
        }
        __syncthreads();

        #pragma unroll
        for (int kk = 0; kk < PTK; kk++) {
            float4 a0 = *(const float4*)&As[kk][mf];
            float4 a1 = *(const float4*)&As[kk][mf + 4];
            float4 b0 = *(const float4*)&Bs[kk][nf];
            float4 b1 = *(const float4*)&Bs[kk][nf + 4];
            ull ap[4] = { pk(a0.x, a0.y), pk(a0.z, a0.w), pk(a1.x, a1.y), pk(a1.z, a1.w) };
            float bn[8] = { b0.x, b0.y, b0.z, b0.w, b1.x, b1.y, b1.z, b1.w };
            #pragma unroll
            for (int n = 0; n < 8; n++) {
                ull bp = pk(bn[n], bn[n]);
                #pragma unroll
                for (int m = 0; m < 4; m++) fma2(acc[n][m], ap[m], bp);
            }
        }
        __syncthreads();
    }

    float* ob = out + ((size_t)b * CC + o0 + nf) * NPIX + p0 + mf;
    #pragma unroll
    for (int n = 0; n < 8; n++) {
        float r[8];
        #pragma unroll
        for (int m = 0; m < 4; m++) upk(acc[n][m], r[2 * m], r[2 * m + 1]);
        *(float4*)&ob[(size_t)n * NPIX]     = make_float4(r[0], r[1], r[2], r[3]);
        *(float4*)&ob[(size_t)n * NPIX + 4] = make_float4(r[4], r[5], r[6], r[7]);
    }
}

// ---------------- launch ----------------
extern "C" void kernel_launch(void* const* d_in, const int* in_sizes, int n_in,
                              void* d_out, int out_size)
{
    const float* x    = (const float*)d_in[0];
    const float* temp = (const float*)d_in[1];
    const float* w1   = (const float*)d_in[2];
    const float* b1   = (const float*)d_in[3];
    const float* bng  = (const float*)d_in[4];
    const float* bnb  = (const float*)d_in[5];
    const float* bnm  = (const float*)d_in[6];
    const float* bnv  = (const float*)d_in[7];
    const float* w2   = (const float*)d_in[8];
    const float* b2   = (const float*)d_in[9];
    const float* pw   = (const float*)d_in[10];
    float* out = (float*)d_out;

    const int GRAM_SMEM = (CPH * APITCH + GSL * BPITCH) * 4;
    const int OUT2_SMEM = CPH * CPH * 2 * 8 + CPH * ZPITCH * 8;
    const int GATE_SMEM = (CC * XPITCH * 2 + CRR * 257 + CC * 17 + CRR * 33) * 4;

    cudaFuncSetAttribute(k_fft2,     cudaFuncAttributeMaxDynamicSharedMemorySize, FFT_SMEM_BYTES);
    cudaFuncSetAttribute(k_ifft2abs, cudaFuncAttributeMaxDynamicSharedMemorySize, FFT_SMEM_BYTES);
    cudaFuncSetAttribute(k_rowfft_z, cudaFuncAttributeMaxDynamicSharedMemorySize, RZ_SMEM_BYTES);
    cudaFuncSetAttribute(k_gram,  cudaFuncAttributeMaxDynamicSharedMemorySize, GRAM_SMEM);
    cudaFuncSetAttribute(k_out2,  cudaFuncAttributeMaxDynamicSharedMemorySize, OUT2_SMEM);
    cudaFuncSetAttribute(k_gate,  cudaFuncAttributeMaxDynamicSharedMemorySize, GATE_SMEM);

    k_zero<<<(BB * HD * CPH * CPH + 255) / 256, 256>>>();
    k_rowfft_z<<<dim3(4, NIMG), 256, RZ_SMEM_BYTES>>>(x);
    k_fft2<<<NIMG, 1024, FFT_SMEM_BYTES>>>(x);
    k_gram<<<dim3(NPIX / GSL, BB * HD), 256, GRAM_SMEM>>>(x);
    k_attn<<<BB * HD, 1024>>>(temp);
    k_out2<<<dim3(NPIX / OPX, BB * HD), 256, OUT2_SMEM>>>();
    k_gate<<<dim3(NPIX / GPIX, BB), 256, GATE_SMEM>>>(w1, b1, bng, bnb, bnm, bnv, w2, b2);
    k_ifft2abs<<<NIMG, 1024, FFT_SMEM_BYTES>>>();
    k_proj<<<dim3(NPIX / PTM, CC / PTN, BB), 256>>>(pw, out);
}

// round 15
// speedup vs baseline: 1.0183x; 1.0183x over previous
#include <cuda_runtime.h>
#include <math.h>

#define BB 4
#define CC 256
#define NPIX 16384
#define HD 8
#define CPH 32
#define CRR 16
#define NIMG 1024
#define PITCH 129

typedef unsigned long long ull;

__device__ __forceinline__ ull pk(float lo, float hi) {
    ull r; asm("mov.b64 %0, {%1,%2};" : "=l"(r) : "f"(lo), "f"(hi)); return r;
}
__device__ __forceinline__ void upk(ull v, float& lo, float& hi) {
    asm("mov.b64 {%0,%1}, %2;" : "=f"(lo), "=f"(hi) : "l"(v));
}
__device__ __forceinline__ void fma2(ull& d, ull a, ull b) {
    asm("fma.rn.f32x2 %0, %1, %2, %3;" : "=l"(d) : "l"(a), "l"(b), "l"(d));
}

// ---------------- device scratch ----------------
__device__ float2 g_Xc[NIMG * NPIX];
__device__ float2 g_z[NIMG * NPIX];
__device__ float2 g_gXc[NIMG * NPIX];
__device__ float  g_outf[NIMG * NPIX];
__device__ float  g_outfl[NIMG * NPIX];
__device__ float  g_gram[BB * HD * CPH * CPH];
__device__ float  g_norm2[BB * CC];
__device__ float2 g_attn2[BB * HD * CPH * CPH];

__device__ __forceinline__ int brev3(int t) { return ((t & 1) << 2) | (t & 2) | ((t >> 2) & 1); }

// ---------------- 16-point FFT fully in registers ----------------
template<bool INV>
__device__ __forceinline__ void fft16_reg(float* xr, float* xi)
{
    #define SW_(i,j) { float t_=xr[i]; xr[i]=xr[j]; xr[j]=t_; t_=xi[i]; xi[i]=xi[j]; xi[j]=t_; }
    SW_(1,8) SW_(2,4) SW_(3,12) SW_(5,10) SW_(7,14) SW_(11,13)
    #undef SW_
    const float S = INV ? 1.f : -1.f;
    #pragma unroll
    for (int i = 0; i < 16; i += 2) {
        float ur = xr[i], ui = xi[i], vr = xr[i+1], vi = xi[i+1];
        xr[i] = ur + vr; xi[i] = ui + vi;
        xr[i+1] = ur - vr; xi[i+1] = ui - vi;
    }
    #pragma unroll
    for (int i = 0; i < 16; i += 4) {
        { float ur = xr[i], ui = xi[i], vr = xr[i+2], vi = xi[i+2];
          xr[i] = ur + vr; xi[i] = ui + vi; xr[i+2] = ur - vr; xi[i+2] = ui - vi; }
        { float ur = xr[i+1], ui = xi[i+1], vr = xr[i+3], vi = xi[i+3];
          float tr = -S * vi, ti = S * vr;
          xr[i+1] = ur + tr; xi[i+1] = ui + ti; xr[i+3] = ur - tr; xi[i+3] = ui - ti; }
    }
    {
        const float H = 0.70710678118654752f;
        const float w8r[4] = {1.f, H, 0.f, -H};
        const float w8i[4] = {0.f, H, 1.f, H};
        #pragma unroll
        for (int i = 0; i < 16; i += 8) {
            #pragma unroll
            for (int p = 0; p < 4; p++) {
                float wr = w8r[p], wi = S * w8i[p];
                float ur = xr[i+p], ui = xi[i+p], vr = xr[i+p+4], vi = xi[i+p+4];
                float tr = vr * wr - vi * wi, ti = vr * wi + vi * wr;
                xr[i+p] = ur + tr; xi[i+p] = ui + ti;
                xr[i+p+4] = ur - tr; xi[i+p+4] = ui - ti;
            }
        }
    }
    {
        const float C1 = 0.92387953251128674f, C2 = 0.70710678118654752f, C3 = 0.38268343236508978f;
        const float w16r[8] = {1.f, C1, C2, C3, 0.f, -C3, -C2, -C1};
        const float w16i[8] = {0.f, C3, C2, C1, 1.f, C1, C2, C3};
        #pragma unroll
        for (int p = 0; p < 8; p++) {
            float wr = w16r[p], wi = S * w16i[p];
            float ur = xr[p], ui = xi[p], vr = xr[p+8], vi = xi[p+8];
            float tr = vr * wr - vi * wi, ti = vr * wi + vi * wr;
            xr[p] = ur + tr; xi[p] = ui + ti;
            xr[p+8] = ur - tr; xi[p+8] = ui - ti;
        }
    }
}

// ---------------- 8-point cross-lane DIF FFT via shfl ----------------
template<bool INV>
__device__ __forceinline__ void xfft8(float* yr, float* yi, int t)
{
    const float S = INV ? 1.f : -1.f;
    const float H = 0.70710678118654752f;
    {
        int p = t & 3;
        float wr = (p == 0) ? 1.f : (p == 1) ? H : (p == 2) ? 0.f : -H;
        float wi = S * ((p == 0) ? 0.f : (p == 2) ? 1.f : H);
        bool hi = (t & 4) != 0;
        #pragma unroll
        for (int m = 0; m < 16; m++) {
            float pr = __shfl_xor_sync(0xffffffffu, yr[m], 4);
            float pi = __shfl_xor_sync(0xffffffffu, yi[m], 4);
            if (!hi) { yr[m] += pr; yi[m] += pi; }
            else {
                float dr = pr - yr[m], di = pi - yi[m];
                yr[m] = dr * wr - di * wi; yi[m] = dr * wi + di * wr;
            }
        }
    }
    {
        bool hi = (t & 2) != 0, odd = (t & 1) != 0;
        #pragma unroll
        for (int m = 0; m < 16; m++) {
            float pr = __shfl_xor_sync(0xffffffffu, yr[m], 2);
            float pi = __shfl_xor_sync(0xffffffffu, yi[m], 2);
            if (!hi) { yr[m] += pr; yi[m] += pi; }
            else {
                float dr = pr - yr[m], di = pi - yi[m];
                if (!odd) { yr[m] = dr; yi[m] = di; }
                else      { yr[m] = -S * di; yi[m] = S * dr; }
            }
        }
    }
    {
        bool hi = (t & 1) != 0;
        #pragma unroll
        for (int m = 0; m < 16; m++) {
            float pr = __shfl_xor_sync(0xffffffffu, yr[m], 1);
            float pi = __shfl_xor_sync(0xffffffffu, yi[m], 1);
            if (!hi) { yr[m] += pr; yi[m] += pi; }
            else     { yr[m] = pr - yr[m]; yi[m] = pi - yi[m]; }
        }
    }
}

// ---------------- 128-pt FFT over smem tile; group g, lane t in [0,8) ----------
template<bool INV, bool COLS>
__device__ __forceinline__ void fft128_reg(float* re, float* im, const float* twc, int g, int t)
{
    float xr[16], xi[16];
    #pragma unroll
    for (int m = 0; m < 16; m++) {
        int n = t + 8 * m;
        int idx = COLS ? (n * PITCH + g) : (g * PITCH + n);
        xr[m] = re[idx]; xi[m] = im[idx];
    }
    fft16_reg<INV>(xr, xi);
    #pragma unroll
    for (int m = 0; m < 16; m++) {
        int j = m * t;
        float cr = twc[2 * j], ci = twc[2 * j + 1];
        float wi = INV ? ci : -ci;
        float a = xr[m], b = xi[m];
        xr[m] = a * cr - b * wi;
        xi[m] = a * wi + b * cr;
    }
    xfft8<INV>(xr, xi, t);
    int s = brev3(t);
    #pragma unroll
    for (int m = 0; m < 16; m++) {
        int f = m + 16 * s;
        int idx = COLS ? (f * PITCH + g) : (g * PITCH + f);
        if (INV) { re[idx] = xr[m] * 0.0078125f; im[idx] = xi[m] * 0.0078125f; }
        else     { re[idx] = xr[m];              im[idx] = xi[m]; }
    }
}

#define FFT_SMEM_FLOATS (2 * 128 * PITCH + 512)
#define FFT_SMEM_BYTES  (FFT_SMEM_FLOATS * 4)
#define RZ_SMEM_FLOATS  (2 * 32 * PITCH + 512)
#define RZ_SMEM_BYTES   (RZ_SMEM_FLOATS * 4)

__device__ __forceinline__ void build_tw128(float* twc)
{
    for (int a = threadIdx.x; a < 128; a += blockDim.x) {
        float s, c;
        sincospif((float)a / 64.0f, &s, &c);
        twc[2 * a] = c; twc[2 * a + 1] = s;
    }
}

// ---------------- zero accumulators ----------------
__global__ void k_zero()
{
    int i = blockIdx.x * blockDim.x + threadIdx.x;
    if (i < BB * HD * CPH * CPH) g_gram[i] = 0.f;
    if (i < BB * CC) g_norm2[i] = 0.f;
}

// ---------------- gram + norms (f32x2, conflict-free Bf) ----------------
#define GSL 256
#define APITCH 257
#define BPITCH 33
__global__ void __launch_bounds__(256) k_gram(const float* __restrict__ x)
{
    extern __shared__ float sm[];
    float* A  = sm;                        // [32][APITCH]
    float* Bf = sm + CPH * APITCH;         // [GSL][BPITCH] (stride 33 -> conflict-free STS)
    int p0 = blockIdx.x * GSL;
    int bh = blockIdx.y;
    int b = bh >> 3, head = bh & 7;
    const float* xb = x + (size_t)(b * CC + head * CPH) * NPIX;
    int tid = threadIdx.x;

    for (int i = tid; i < CPH * GSL; i += 256) {
        int d = i >> 8, jj = i & 255;
        int p = p0 + jj;
        A[d * APITCH + jj] = xb[(size_t)d * NPIX + p];
        int fr = (128 - (p >> 7)) & 127;
        int fw = (128 - (p & 127)) & 127;
        Bf[jj * BPITCH + d] = xb[(size_t)d * NPIX + fr * 128 + fw];
    }
    __syncthreads();

    if (tid < CPH) {
        float s = 0.f;
        for (int j = 0; j < GSL; j++) { float v = A[tid * APITCH + j]; s += v * v; }
        atomicAdd(&g_norm2[b * CC + head * CPH + tid], s);
    }

    int c0 = (tid >> 4) * 2;
    int d0 = (tid & 15) * 2;
    ull acc0 = 0, acc1 = 0;
    for (int j = 0; j < GSL; j++) {
        float a0 = A[c0 * APITCH + j];
        float a1 = A[(c0 + 1) * APITCH + j];
        float b0 = Bf[j * BPITCH + d0];
        float b1 = Bf[j * BPITCH + d0 + 1];
        ull bp = pk(b0, b1);
        fma2(acc0, pk(a0, a0), bp);
        fma2(acc1, pk(a1, a1), bp);
    }
    float v00, v01, v10, v11;
    upk(acc0, v00, v01); upk(acc1, v10, v11);
    float* G = g_gram + (size_t)bh * CPH * CPH;
    atomicAdd(&G[c0 * CPH + d0], v00);
    atomicAdd(&G[c0 * CPH + d0 + 1], v01);
    atomicAdd(&G[(c0 + 1) * CPH + d0], v10);
    atomicAdd(&G[(c0 + 1) * CPH + d0 + 1], v11);
}

// ---------------- kernel A: row FFT + twiddle + row iFFT -> z (32-row chunks) ----------------
__global__ void __launch_bounds__(256) k_rowfft_z(const float* __restrict__ x)
{
    extern __shared__ float sm[];
    float* re = sm;
    float* im = re + 32 * PITCH;
    float* t1 = im + 32 * PITCH;
    float* t2 = t1 + 256;

    build_tw128(t1);
    for (int a = threadIdx.x; a < 128; a += blockDim.x) {
        float s, c;
        sincospif((float)a / 8192.0f, &s, &c);
        t2[2 * a] = c; t2[2 * a + 1] = s;
    }

    int c = blockIdx.x;
    int img = blockIdx.y;
    const float* xin = x + (size_t)img * NPIX + (size_t)c * 32 * 128;
    int tid = threadIdx.x;
    int g = tid >> 3, t = tid & 7;

    #pragma unroll
    for (int it = 0; it < 16; it++) {
        int i = tid + it * 256;
        int lr = i >> 7, k = i & 127;
        re[lr * PITCH + k] = xin[lr * 128 + k];
        im[lr * PITCH + k] = 0.f;
    }
    __syncthreads();

    fft128_reg<false, false>(re, im, t1, g, t);
    __syncthreads();

    #pragma unroll
    for (int it = 0; it < 16; it++) {
        int i = tid + it * 256;
        int lr = i >> 7, f = i & 127;
        int r = c * 32 + lr;
        int j = f * r;
        int a = j >> 7, bI = j & 127;
        float wr = t1[2 * a] * t2[2 * bI] - t1[2 * a + 1] * t2[2 * bI + 1];
        float wi = t1[2 * a] * t2[2 * bI + 1] + t1[2 * a + 1] * t2[2 * bI];
        int idx = lr * PITCH + f;
        float xr_ = re[idx], xi_ = im[idx];
        re[idx] = xr_ * wr - xi_ * wi;
        im[idx] = xr_ * wi + xi_ * wr;
    }
    __syncthreads();

    fft128_reg<true, false>(re, im, t1, g, t);
    __syncthreads();

    float2* Z = g_z + (size_t)img * NPIX;
    #pragma unroll
    for (int it = 0; it < 16; it++) {
        int u = tid + it * 256;
        int lr = u & 31, m1 = u >> 5;
        Z[m1 * 128 + c * 32 + lr] = make_float2(re[lr * PITCH + m1], im[lr * PITCH + m1]);
    }
}

// ---------------- kernel B: full fft2(x) -> Xc ----------------
__global__ void __launch_bounds__(1024, 1) k_fft2(const float* __restrict__ x)
{
    extern __shared__ float sm[];
    float* re = sm;
    float* im = re + 128 * PITCH;
    float* t1 = im + 128 * PITCH;
    build_tw128(t1);

    int img = blockIdx.x;
    const float* xin = x + (size_t)img * NPIX;
    int tid = threadIdx.x;
    int g = tid >> 3, t = tid & 7;

    #pragma unroll
    for (int it = 0; it < 16; it++) {
        int i = tid + it * 1024;
        int r = i >> 7, k = i & 127;
        re[r * PITCH + k] = xin[i];
        im[r * PITCH + k] = 0.f;
    }
    __syncthreads();

    fft128_reg<false, false>(re, im, t1, g, t);
    __syncthreads();
    fft128_reg<false, true>(re, im, t1, g, t);
    __syncthreads();

    float2* Xc = g_Xc + (size_t)img * NPIX;
    #pragma unroll
    for (int it = 0; it < 16; it++) {
        int i = tid + it * 1024;
        int r = i >> 7, k = i & 127;
        Xc[i] = make_float2(re[r * PITCH + k], im[r * PITCH + k]);
    }
}

// ---------------- softmax + 32-pt IFFT of attn ----------------
__global__ void k_attn(const float* __restrict__ temp)
{
    __shared__ float sP[CPH][CPH + 1];
    int bh = blockIdx.x;
    int b = bh >> 3, head = bh & 7;
    int tid = threadIdx.x;
    int c = tid >> 5, d = tid & 31;

    float G = g_gram[(bh * CPH + c) * CPH + d];
    float nc = fmaxf(128.f * sqrtf(g_norm2[b * CC + head * CPH + c]), 1e-12f);
    float nd = fmaxf(128.f * sqrtf(g_norm2[b * CC + head * CPH + d]), 1e-12f);
    float S = temp[head] * 16384.f * G / (nc * nd);

    float m = S;
    #pragma unroll
    for (int o = 16; o; o >>= 1) m = fmaxf(m, __shfl_xor_sync(0xffffffffu, m, o));
    float e = expf(S - m);
    float sum = e;
    #pragma unroll
    for (int o = 16; o; o >>= 1) sum += __shfl_xor_sync(0xffffffffu, sum, o);
    sP[c][d] = e / sum;
    __syncthreads();

    float ar = 0.f, ai = 0.f;
    #pragma unroll
    for (int cp = 0; cp < 32; cp++) {
        float s, cw;
        sincospif((float)(c * cp) / 16.0f, &s, &cw);
        float v = sP[cp][d];
        ar += v * cw - (1.0f / 32.0f) * s;
        ai += v * s + (1.0f / 32.0f) * cw;
    }
    g_attn2[(bh * CPH + c) * CPH + d] = make_float2(ar * (1.f / 32.f), ai * (1.f / 32.f));
}

// ---------------- out_f = | attn2 @ z | ----------------
#define OPX 256
#define ZPITCH 257
__global__ void __launch_bounds__(256) k_out2()
{
    extern __shared__ float smraw[];
    ull*    sAp = (ull*)smraw;
    float2* sZ  = (float2*)(smraw + CPH * CPH * 4);
    int bh = blockIdx.y;
    int b = bh >> 3, head = bh & 7;
    int p0 = blockIdx.x * OPX;
    int tid = threadIdx.x;

    for (int i = tid; i < CPH * CPH; i += 256) {
        float2 a = g_attn2[bh * CPH * CPH + i];
        sAp[i * 2 + 0] = pk(a.x, a.x);
        sAp[i * 2 + 1] = pk(a.y, a.y);
    }
    size_t base = (size_t)(b * CC + head * CPH) * NPIX + p0;
    for (int i = tid; i < CPH * OPX; i += 256) {
        int d = i >> 8, j = i & 255;
        sZ[d * ZPITCH + j] = g_z[base + (size_t)d * NPIX + j];
    }
    __syncthreads();

    int j = tid;
    ull acc[CPH];
    #pragma unroll
    for (int c = 0; c < CPH; c++) acc[c] = 0;

    for (int d = 0; d < CPH; d++) {
        float2 z = sZ[d * ZPITCH + j];
        ull zp = pk(z.x, z.y);
        ull zs = pk(-z.y, z.x);
        const ull* row = sAp + d * 2;
        #pragma unroll
        for (int c = 0; c < CPH; c++) {
            fma2(acc[c], row[c * 64 + 0], zp);
            fma2(acc[c], row[c * 64 + 1], zs);
        }
    }
    #pragma unroll
    for (int c = 0; c < CPH; c++) {
        float ar, ai; upk(acc[c], ar, ai);
        g_outf[(size_t)(b * CC + head * CPH + c) * NPIX + p0 + j] = sqrtf(ar * ar + ai * ai);
    }
}

// ---------------- fused gating ----------------
#define GPIX 32
#define XPITCH 33
__global__ void __launch_bounds__(256) k_gate(const float* __restrict__ w1, const float* __restrict__ b1,
                                              const float* __restrict__ bng, const float* __restrict__ bnb,
                                              const float* __restrict__ bnm, const float* __restrict__ bnv,
                                              const float* __restrict__ w2, const float* __restrict__ b2)
{
    extern __shared__ float sm[];
    float2* sxc = (float2*)sm;
    float*  sw1 = sm + CC * XPITCH * 2;
    float*  sw2 = sw1 + CRR * 257;
    float*  st  = sw2 + CC * 17;

    int b = blockIdx.y;
    int p0 = blockIdx.x * GPIX;
    int tid = threadIdx.x;

    for (int i = tid; i < CRR * CC; i += 256) {
        int j = i >> 8, ch = i & 255;
        sw1[j * 257 + ch] = w1[i];
    }
    for (int i = tid; i < CC * CRR; i += 256) {
        int ch = i >> 4, j = i & 15;
        sw2[ch * 17 + j] = w2[i];
    }
    const float2* Xc = g_Xc + (size_t)b * CC * NPIX;
    for (int i = tid; i < CC * GPIX; i += 256) {
        int ch = i >> 5, p = i & 31;
        sxc[ch * XPITCH + p] = Xc[(size_t)ch * NPIX + p0 + p];
    }
    __syncthreads();

    {
        int j = tid & 15, pp = tid >> 4;
        ull acc = 0;
        for (int ch = 0; ch < CC; ch++) {
            float w = sw1[j * 257 + ch];
            float x0 = sxc[ch * XPITCH + pp].x;
            float x1 = sxc[ch * XPITCH + pp + 16].x;
            fma2(acc, pk(w, w), pk(x0, x1));
        }
        float a0, a1; upk(acc, a0, a1);
        float scale = bng[j] * rsqrtf(bnv[j] + 1e-5f);
        float shift = bnb[j] + (b1[j] - bnm[j]) * scale;
        st[j * 33 + pp]      = fmaxf(a0 * scale + shift, 0.f);
        st[j * 33 + pp + 16] = fmaxf(a1 * scale + shift, 0.f);
    }
    __syncthreads();

    int p = tid & 31, cg = tid >> 5;
    float2* O = g_gXc + (size_t)b * CC * NPIX + p0;
    for (int cc = 0; cc < 32; cc++) {
        int ch = cg * 32 + cc;
        float acc = b2[ch];
        #pragma unroll
        for (int j = 0; j < CRR; j++)
            acc += sw2[ch * 17 + j] * st[j * 33 + p];
        float gate = 1.f / (1.f + __expf(-acc));
        float2 v = sxc[ch * XPITCH + p];
        O[(size_t)ch * NPIX + p] = make_float2(gate * v.x, gate * v.y);
    }
}

// ---------------- ifft2 + abs of gated spectrum ----------------
__global__ void __launch_bounds__(1024, 1) k_ifft2abs()
{
    extern __shared__ float sm[];
    float* re = sm;
    float* im = re + 128 * PITCH;
    float* t1 = im + 128 * PITCH;
    build_tw128(t1);

    int img = blockIdx.x;
    const float2* in = g_gXc + (size_t)img * NPIX;
    int tid = threadIdx.x;
    int g = tid >> 3, t = tid & 7;

    #pragma unroll
    for (int it = 0; it < 16; it++) {
        int i = tid + it * 1024;
        int r = i >> 7, k = i & 127;
        float2 v = in[i];
        re[r * PITCH + k] = v.x;
        im[r * PITCH + k] = v.y;
    }
    __syncthreads();

    fft128_reg<true, false>(re, im, t1, g, t);
    __syncthreads();
    fft128_reg<true, true>(re, im, t1, g, t);
    __syncthreads();

    float* out = g_outfl + (size_t)img * NPIX;
    #pragma unroll
    for (int it = 0; it < 16; it++) {
        int i = tid + it * 1024;
        int r = i >> 7, k = i & 127;
        float a = re[r * PITCH + k], bv = im[r * PITCH + k];
        out[i] = sqrtf(a * a + bv * bv);
    }
}

// ---------------- final projection: 128x128 tile, 8x8/thread, f32x2, prefetched ----------------
#define PTM 128
#define PTN 128
#define PTK 16
#define SPITCH 132
__global__ void __launch_bounds__(256) k_proj(const float* __restrict__ pw, float* __restrict__ out)
{
    __shared__ float As[PTK][SPITCH];
    __shared__ float Bs[PTK][SPITCH];
    int b = blockIdx.z;
    int p0 = blockIdx.x * PTM;
    int o0 = blockIdx.y * PTN;
    int tid = threadIdx.x;
    int mf = (tid & 15) * 8;
    int nf = (tid >> 4) * 8;

    // per-thread load coordinates
    int ka0 = tid >> 5,        pa0 = (tid & 31) * 4;
    int ka1 = (tid + 256) >> 5, pa1 = ((tid + 256) & 31) * 4;
    int ob0 = tid & 127,       kb0 = (tid >> 7) * 4;
    int ob1 = (tid + 256) & 127, kb1 = ((tid + 256) >> 7) * 4;

    ull acc[8][4];
    #pragma unroll
    for (int n = 0; n < 8; n++)
        #pragma unroll
        for (int m = 0; m < 4; m++) acc[n][m] = 0;

    float4 va0, va1, vb0, vb1;
    // prefetch chunk 0
    {
        const float* src = g_outf;
        va0 = *(const float4*)&src[((size_t)b * CC + ka0) * NPIX + p0 + pa0];
        va1 = *(const float4*)&src[((size_t)b * CC + ka1) * NPIX + p0 + pa1];
        vb0 = *(const float4*)&pw[(size_t)(o0 + ob0) * 512 + kb0];
        vb1 = *(const float4*)&pw[(size_t)(o0 + ob1) * 512 + kb1];
    }

    for (int k0 = 0; k0 < 512; k0 += PTK) {
        // stage current chunk to smem
        *(float4*)&As[ka0][pa0] = va0;
        *(float4*)&As[ka1][pa1] = va1;
        Bs[kb0 + 0][ob0] = vb0.x; Bs[kb0 + 1][ob0] = vb0.y;
        Bs[kb0 + 2][ob0] = vb0.z; Bs[kb0 + 3][ob0] = vb0.w;
        Bs[kb1 + 0][ob1] = vb1.x; Bs[kb1 + 1][ob1] = vb1.y;
        Bs[kb1 + 2][ob1] = vb1.z; Bs[kb1 + 3][ob1] = vb1.w;
        __syncthreads();

        // prefetch next chunk (overlaps with compute below)
        int kn = k0 + PTK;
        if (kn < 512) {
            const float* src = (kn < 256) ? g_outf : g_outfl;
            int cb = kn & 255;
            va0 = *(const float4*)&src[((size_t)b * CC + cb + ka0) * NPIX + p0 + pa0];
            va1 = *(const float4*)&src[((size_t)b * CC + cb + ka1) * NPIX + p0 + pa1];
            vb0 = *(const float4*)&pw[(size_t)(o0 + ob0) * 512 + kn + kb0];
            vb1 = *(const float4*)&pw[(size_t)(o0 + ob1) * 512 + kn + kb1];
        }

        #pragma unroll
        for (int kk = 0; kk < PTK; kk++) {
            float4 a0 = *(const float4*)&As[kk][mf];
            float4 a1 = *(const float4*)&As[kk][mf + 4];
            float4 b0 = *(const float4*)&Bs[kk][nf];
            float4 b1 = *(const float4*)&Bs[kk][nf + 4];
            ull ap[4] = { pk(a0.x, a0.y), pk(a0.z, a0.w), pk(a1.x, a1.y), pk(a1.z, a1.w) };
            float bn[8] = { b0.x, b0.y, b0.z, b0.w, b1.x, b1.y, b1.z, b1.w };
            #pragma unroll
            for (int n = 0; n < 8; n++) {
                ull bp = pk(bn[n], bn[n]);
                #pragma unroll
                for (int m = 0; m < 4; m++) fma2(acc[n][m], ap[m], bp);
            }
        }
        __syncthreads();
    }

    float* ob = out + ((size_t)b * CC + o0 + nf) * NPIX + p0 + mf;
    #pragma unroll
    for (int n = 0; n < 8; n++) {
        float r[8];
        #pragma unroll
        for (int m = 0; m < 4; m++) upk(acc[n][m], r[2 * m], r[2 * m + 1]);
        *(float4*)&ob[(size_t)n * NPIX]     = make_float4(r[0], r[1], r[2], r[3]);
        *(float4*)&ob[(size_t)n * NPIX + 4] = make_float4(r[4], r[5], r[6], r[7]);
    }
}

// ---------------- launch ----------------
extern "C" void kernel_launch(void* const* d_in, const int* in_sizes, int n_in,
                              void* d_out, int out_size)
{
    const float* x    = (const float*)d_in[0];
    const float* temp = (const float*)d_in[1];
    const float* w1   = (const float*)d_in[2];
    const float* b1   = (const float*)d_in[3];
    const float* bng  = (const float*)d_in[4];
    const float* bnb  = (const float*)d_in[5];
    const float* bnm  = (const float*)d_in[6];
    const float* bnv  = (const float*)d_in[7];
    const float* w2   = (const float*)d_in[8];
    const float* b2   = (const float*)d_in[9];
    const float* pw   = (const float*)d_in[10];
    float* out = (float*)d_out;

    const int GRAM_SMEM = (CPH * APITCH + GSL * BPITCH) * 4;
    const int OUT2_SMEM = CPH * CPH * 2 * 8 + CPH * ZPITCH * 8;
    const int GATE_SMEM = (CC * XPITCH * 2 + CRR * 257 + CC * 17 + CRR * 33) * 4;

    cudaFuncSetAttribute(k_fft2,     cudaFuncAttributeMaxDynamicSharedMemorySize, FFT_SMEM_BYTES);
    cudaFuncSetAttribute(k_ifft2abs, cudaFuncAttributeMaxDynamicSharedMemorySize, FFT_SMEM_BYTES);
    cudaFuncSetAttribute(k_rowfft_z, cudaFuncAttributeMaxDynamicSharedMemorySize, RZ_SMEM_BYTES);
    cudaFuncSetAttribute(k_gram,  cudaFuncAttributeMaxDynamicSharedMemorySize, GRAM_SMEM);
    cudaFuncSetAttribute(k_out2,  cudaFuncAttributeMaxDynamicSharedMemorySize, OUT2_SMEM);
    cudaFuncSetAttribute(k_gate,  cudaFuncAttributeMaxDynamicSharedMemorySize, GATE_SMEM);

    // reordered: k_gram moved up so the fixed ncu capture slot lands on a different kernel
    k_zero<<<(BB * HD * CPH * CPH + 255) / 256, 256>>>();
    k_gram<<<dim3(NPIX / GSL, BB * HD), 256, GRAM_SMEM>>>(x);
    k_rowfft_z<<<dim3(4, NIMG), 256, RZ_SMEM_BYTES>>>(x);
    k_fft2<<<NIMG, 1024, FFT_SMEM_BYTES>>>(x);
    k_attn<<<BB * HD, 1024>>>(temp);
    k_out2<<<dim3(NPIX / OPX, BB * HD), 256, OUT2_SMEM>>>();
    k_gate<<<dim3(NPIX / GPIX, BB), 256, GATE_SMEM>>>(w1, b1, bng, bnb, bnm, bnv, w2, b2);
    k_ifft2abs<<<NIMG, 1024, FFT_SMEM_BYTES>>>();
    k_proj<<<dim3(NPIX / PTM, CC / PTN, BB), 256>>>(pw, out);
}